// round 15
// baseline (speedup 1.0000x reference)
#include <cuda_runtime.h>
#include <cuda_bf16.h>
#include <cuda_fp16.h>
#include <cstdint>

// ---------------------------------------------------------------------------
// GCN: 3 layers. out = Ahat @ (X @ W) + b, relu on layers 1,2.
//
// R15 = R14 + (1) gemm1 uses single-fp16 A (X rounded once) vs W hi/lo:
// 2 MMAs/k-step, half the A staging; (2) F=128 aggs use 2 warps per node
// (64 cols each) for 2x gather MLP. CSR chain / fork-join unchanged.
// ---------------------------------------------------------------------------

#define N_NODES 50000
#define N_EDGES 800000

// ----- device scratch (static globals: allocation-free) -----
__device__ unsigned long long g_deg64[N_NODES];   // count<<40 | w_sum*2^20
__device__ float g_dis[N_NODES];
__device__ int   g_offsets[N_NODES];
__device__ int   g_blocksums[64];
__device__ uint2 g_edge[N_EDGES];        // .x = src, .y = float bits of norm
__device__ __half g_bufHa[(size_t)N_NODES * 128];
__device__ __half g_bufHb[(size_t)N_NODES * 128];
__device__ __half g_Whi[256 * 128 + 128 * 128 + 128 * 64];
__device__ __half g_Wlo[256 * 128 + 128 * 128 + 128 * 64];

#define W1_OFF 0
#define W2_OFF (256 * 128)
#define W3_OFF (256 * 128 + 128 * 128)
#define W_TOTAL (256 * 128 + 128 * 128 + 128 * 64)

// ---------------------------------------------------------------------------
// Setup kernels (R14 verbatim)
// ---------------------------------------------------------------------------
__global__ void k_deg_count(const int* __restrict__ ei,
                            const float* __restrict__ ew, int E) {
    int i = blockIdx.x * blockDim.x + threadIdx.x;
    int e = i * 2;
    if (e + 1 < E) {
        int2   d2 = *(const int2*)(ei + E + e);
        float2 w2 = *(const float2*)(ew + e);
        unsigned long long v0 = (1ULL << 40) |
            (unsigned long long)(w2.x * 1048576.0f);
        unsigned long long v1 = (1ULL << 40) |
            (unsigned long long)(w2.y * 1048576.0f);
        atomicAdd(&g_deg64[d2.x], v0);
        atomicAdd(&g_deg64[d2.y], v1);
    } else if (e < E) {
        unsigned long long v = (1ULL << 40) |
            (unsigned long long)(ew[e] * 1048576.0f);
        atomicAdd(&g_deg64[ei[E + e]], v);
    }
}

__global__ void k_scan1(int n) {
    __shared__ int sh[1024];
    int tid = threadIdx.x;
    int gid = blockIdx.x * 1024 + tid;
    int v = 0;
    if (gid < n) {
        unsigned long long pk = g_deg64[gid];
        v = (int)(pk >> 40);
        float deg = (float)(pk & ((1ULL << 40) - 1)) * (1.0f / 1048576.0f);
        g_dis[gid] = rsqrtf(deg + 1.0f);
    }
    sh[tid] = v;
    __syncthreads();
    for (int off = 1; off < 1024; off <<= 1) {
        int t = (tid >= off) ? sh[tid - off] : 0;
        __syncthreads();
        sh[tid] += t;
        __syncthreads();
    }
    int incl = sh[tid];
    if (gid < n) g_offsets[gid] = incl - v;
    if (tid == 1023) g_blocksums[blockIdx.x] = incl;
}

__global__ void k_scan23(int n, int nb) {
    __shared__ int sh[64];
    int tid = threadIdx.x;
    if (tid < 64) sh[tid] = (tid < nb) ? g_blocksums[tid] : 0;
    __syncthreads();
    if (tid == 0) {
        int run = 0;
        for (int i = 0; i < nb; i++) { int t = sh[i]; sh[i] = run; run += t; }
    }
    __syncthreads();
    int gid = blockIdx.x * 1024 + tid;
    if (gid < n) g_offsets[gid] += sh[blockIdx.x];
}

__global__ void k_scatter(const int* __restrict__ ei,
                          const float* __restrict__ ew, int E) {
    int i = blockIdx.x * blockDim.x + threadIdx.x;
    int e = i * 2;
    if (e + 1 < E) {
        int2   s2 = *(const int2*)(ei + e);
        int2   d2 = *(const int2*)(ei + E + e);
        float2 w2 = *(const float2*)(ew + e);
        float ds0 = g_dis[s2.x], dd0 = g_dis[d2.x];
        float ds1 = g_dis[s2.y], dd1 = g_dis[d2.y];
        int pos0 = atomicAdd(&g_offsets[d2.x], 1);
        int pos1 = atomicAdd(&g_offsets[d2.y], 1);
        g_edge[pos0] = make_uint2((uint32_t)s2.x,
                                  __float_as_uint(ds0 * w2.x * dd0));
        g_edge[pos1] = make_uint2((uint32_t)s2.y,
                                  __float_as_uint(ds1 * w2.y * dd1));
    } else if (e < E) {
        int s = ei[e];
        int d = ei[E + e];
        int pos = atomicAdd(&g_offsets[d], 1);
        float nw = g_dis[s] * ew[e] * g_dis[d];
        g_edge[pos] = make_uint2((uint32_t)s, __float_as_uint(nw));
    }
}

// Convert all three W matrices fp32 -> fp16 hi/lo (once per call).
__global__ void k_convW(const float* __restrict__ W1, const float* __restrict__ W2,
                        const float* __restrict__ W3) {
    int i = blockIdx.x * blockDim.x + threadIdx.x;
    if (i >= W_TOTAL) return;
    float v;
    if (i < W2_OFF)       v = W1[i];
    else if (i < W3_OFF)  v = W2[i - W2_OFF];
    else                  v = W3[i - W3_OFF];
    __half h = __float2half_rn(v);
    __half l = __float2half_rn(v - __half2float(h));
    g_Whi[i] = h;
    g_Wlo[i] = l;
}

// ---------------------------------------------------------------------------
// Tensor-core GEMM helpers (fp16 path)
// ---------------------------------------------------------------------------
__device__ __forceinline__ uint32_t smem_u32(const void* p) {
    return (uint32_t)__cvta_generic_to_shared(p);
}

__device__ __forceinline__ void ldsm4(uint32_t a[4], uint32_t addr) {
    asm volatile("ldmatrix.sync.aligned.m8n8.x4.shared.b16 {%0,%1,%2,%3}, [%4];"
                 : "=r"(a[0]), "=r"(a[1]), "=r"(a[2]), "=r"(a[3]) : "r"(addr));
}

__device__ __forceinline__ void ldsm4t(uint32_t a[4], uint32_t addr) {
    asm volatile("ldmatrix.sync.aligned.m8n8.x4.trans.shared.b16 {%0,%1,%2,%3}, [%4];"
                 : "=r"(a[0]), "=r"(a[1]), "=r"(a[2]), "=r"(a[3]) : "r"(addr));
}

__device__ __forceinline__ void mma16816h(float c[4], const uint32_t a[4],
                                          const uint32_t b[2]) {
    asm volatile(
        "mma.sync.aligned.m16n8k16.row.col.f32.f16.f16.f32 "
        "{%0,%1,%2,%3}, {%4,%5,%6,%7}, {%8,%9}, {%0,%1,%2,%3};"
        : "+f"(c[0]), "+f"(c[1]), "+f"(c[2]), "+f"(c[3])
        : "r"(a[0]), "r"(a[1]), "r"(a[2]), "r"(a[3]), "r"(b[0]), "r"(b[1]));
}

// ---------------------------------------------------------------------------
// GEMM (shared for all layers): A = fp16 (gmem or staged), W fp16 hi/lo,
// 2 MMAs per k-step. Layer 1 uses the fp32-input variant below.
// Block: 256 threads = 8 warps (2 M x 4 N). BM=64, BK=64.
// ---------------------------------------------------------------------------
template <int K, int FOUT, bool A_FP32>
__launch_bounds__(256, 2)
__global__ void k_gemm(const void* __restrict__ Ag,
                       const __half* __restrict__ Whi,
                       const __half* __restrict__ Wlo,
                       __half* __restrict__ Yh, int nrows) {
    constexpr int BM = 64, BK = 64, BN = FOUT;
    constexpr int WN = BN / 4;
    constexpr int NT = WN / 8;
    constexpr int NG = WN / 16;
    constexpr int BCH = BN / 8;
    constexpr int BROWB = BN * 2;

    __shared__ __half Ah[BM * BK];
    __shared__ __half Bhi[BK * BN];
    __shared__ __half Blo[BK * BN];

    const int tid  = threadIdx.x;
    const int lane = tid & 31;
    const int w    = tid >> 5;
    const int wm   = (w & 1) * 32;
    const int wn   = (w >> 1) * WN;
    const int row0 = blockIdx.x * BM;

    float acc[2][NT][4];
#pragma unroll
    for (int mt = 0; mt < 2; mt++)
#pragma unroll
        for (int nt = 0; nt < NT; nt++)
#pragma unroll
            for (int j = 0; j < 4; j++) acc[mt][nt][j] = 0.0f;

    const uint32_t sAh = smem_u32(Ah);
    const uint32_t sBhi = smem_u32(Bhi), sBlo = smem_u32(Blo);

    for (int k0 = 0; k0 < K; k0 += BK) {
        // ---- stage A ----
#pragma unroll
        for (int i = 0; i < 2; i++) {          // 512 16B chunks / 256 threads
            int idx = tid + i * 256;
            int r = idx >> 3, c = idx & 7;
            int gr = row0 + r;
            uint4 v;
            if constexpr (A_FP32) {
                // load 8 fp32, round once to fp16
                if (gr < nrows) {
                    const float4* p = (const float4*)((const float*)Ag +
                                                      (size_t)gr * K + k0 + c * 8);
                    float4 f0 = p[0], f1 = p[1];
                    __half2 h0 = __floats2half2_rn(f0.x, f0.y);
                    __half2 h1 = __floats2half2_rn(f0.z, f0.w);
                    __half2 h2 = __floats2half2_rn(f1.x, f1.y);
                    __half2 h3 = __floats2half2_rn(f1.z, f1.w);
                    v = make_uint4(*(uint32_t*)&h0, *(uint32_t*)&h1,
                                   *(uint32_t*)&h2, *(uint32_t*)&h3);
                } else {
                    v = make_uint4(0, 0, 0, 0);
                }
            } else {
                v = (gr < nrows)
                    ? *(const uint4*)((const __half*)Ag + (size_t)gr * K + k0 + c * 8)
                    : make_uint4(0, 0, 0, 0);
            }
            int dst = r * 128 + ((c ^ (r & 7)) << 4);
            *(uint4*)((char*)Ah + dst) = v;
        }
        // ---- stage B: fp16 hi/lo copies, swizzled ----
        {
            constexpr int CPB = BK * BCH;
#pragma unroll
            for (int i = 0; i < (2 * CPB) / 256; i++) {
                int idx = tid + i * 256;
                int buf = idx / CPB;
                int rem = idx - buf * CPB;
                int kr = rem / BCH, c = rem % BCH;
                const uint4* src = (const uint4*)(buf ? Wlo : Whi);
                uint4 v = src[(size_t)(k0 + kr) * BCH + c];
                int dst = kr * BROWB + ((c ^ (kr & 7)) << 4);
                *(uint4*)((char*)(buf ? Blo : Bhi) + dst) = v;
            }
        }
        __syncthreads();

#pragma unroll
        for (int kk = 0; kk < BK / 16; kk++) {
            uint32_t a[2][4];
#pragma unroll
            for (int mt = 0; mt < 2; mt++) {
                int r = wm + mt * 16 + (lane & 15);
                int c = kk * 2 + (lane >> 4);
                uint32_t off = (uint32_t)(r * 128 + ((c ^ (r & 7)) << 4));
                ldsm4(a[mt], sAh + off);
            }
            uint32_t bh[NG][4], bl[NG][4];
#pragma unroll
            for (int g = 0; g < NG; g++) {
                int kr = kk * 16 + (lane & 15);
                int c = (wn >> 3) + g * 2 + (lane >> 4);
                uint32_t off = (uint32_t)(kr * BROWB + ((c ^ (kr & 7)) << 4));
                ldsm4t(bh[g], sBhi + off);
                ldsm4t(bl[g], sBlo + off);
            }
#pragma unroll
            for (int mt = 0; mt < 2; mt++)
#pragma unroll
                for (int nt = 0; nt < NT; nt++) {
                    const uint32_t* bhp = &bh[nt >> 1][(nt & 1) * 2];
                    const uint32_t* blp = &bl[nt >> 1][(nt & 1) * 2];
                    mma16816h(acc[mt][nt], a[mt], bhp);   // A*Whi
                    mma16816h(acc[mt][nt], a[mt], blp);   // A*Wlo
                }
        }
        __syncthreads();
    }

#pragma unroll
    for (int mt = 0; mt < 2; mt++) {
        int r = row0 + wm + mt * 16 + (lane >> 2);
#pragma unroll
        for (int nt = 0; nt < NT; nt++) {
            int cc = wn + nt * 8 + (lane & 3) * 2;
            if (r < nrows)
                *(__half2*)(Yh + (size_t)r * FOUT + cc) =
                    __floats2half2_rn(acc[mt][nt][0], acc[mt][nt][1]);
            if (r + 8 < nrows)
                *(__half2*)(Yh + (size_t)(r + 8) * FOUT + cc) =
                    __floats2half2_rn(acc[mt][nt][2], acc[mt][nt][3]);
        }
    }
}

// ---------------------------------------------------------------------------
// F=128 aggregation, 2 warps per node (each owns 64 cols, 4B/lane gathers).
// fp16 out (feeds GEMM). RELU always on (layers 1,2).
// ---------------------------------------------------------------------------
__launch_bounds__(256)
__global__ void k_agg128(const __half* __restrict__ H, const float* __restrict__ bias,
                         __half* __restrict__ outH, int n) {
    int gw   = (blockIdx.x * blockDim.x + threadIdx.x) >> 5;
    int lane = threadIdx.x & 31;
    int node = gw >> 1;
    if (node >= n) return;
    int col = (gw & 1) * 64 + lane * 2;

    int s = (node == 0) ? 0 : g_offsets[node - 1];
    int e = g_offsets[node];

    float2 acc = make_float2(0.f, 0.f);
    for (int j = s; j < e; j++) {
        uint2  ed = g_edge[j];
        float  nw = __uint_as_float(ed.y);
        uint32_t raw = *(const uint32_t*)(H + (size_t)ed.x * 128 + col);
        float2 f = __half22float2(*(__half2*)&raw);
        acc.x += nw * f.x; acc.y += nw * f.y;
    }
    float dv = g_dis[node];
    float sw = dv * dv;
    uint32_t raw = *(const uint32_t*)(H + (size_t)node * 128 + col);
    float2 f = __half22float2(*(__half2*)&raw);
    acc.x += sw * f.x; acc.y += sw * f.y;
    float2 b = *(const float2*)(bias + col);
    acc.x = fmaxf(acc.x + b.x, 0.f);
    acc.y = fmaxf(acc.y + b.y, 0.f);
    __half2 p = __floats2half2_rn(acc.x, acc.y);
    *(uint32_t*)(outH + (size_t)node * 128 + col) = *(uint32_t*)&p;
}

// ---------------------------------------------------------------------------
// Final F=64 aggregation: 1 warp per node, fp32 out, no relu; zeroes g_deg64.
// ---------------------------------------------------------------------------
__launch_bounds__(256)
__global__ void k_agg_final(const __half* __restrict__ H,
                            const float* __restrict__ bias,
                            float* __restrict__ out, int n) {
    constexpr int F = 64;
    int warp = (blockIdx.x * blockDim.x + threadIdx.x) >> 5;
    int lane = threadIdx.x & 31;
    if (warp >= n) return;

    int s = (warp == 0) ? 0 : g_offsets[warp - 1];
    int e = g_offsets[warp];
    int col = lane * 2;

    if (lane == 0) g_deg64[warp] = 0ULL;   // reset for next invocation

    float2 acc = make_float2(0.f, 0.f);
    for (int j = s; j < e; j++) {
        uint2  ed = g_edge[j];
        float  nw = __uint_as_float(ed.y);
        uint32_t raw = *(const uint32_t*)(H + (size_t)ed.x * F + col);
        float2 f0 = __half22float2(*(__half2*)&raw);
        acc.x += nw * f0.x; acc.y += nw * f0.y;
    }
    float dv = g_dis[warp];
    float sw = dv * dv;
    uint32_t raw = *(const uint32_t*)(H + (size_t)warp * F + col);
    float2 f0 = __half22float2(*(__half2*)&raw);
    acc.x += sw * f0.x; acc.y += sw * f0.y;
    float2 b = *(const float2*)(bias + col);
    acc.x += b.x; acc.y += b.y;
    *(float2*)(out + (size_t)warp * F + col) = acc;
}

// ---------------------------------------------------------------------------
// Launch: fork-join (branch A: CSR build; branch B: convW + GEMM1).
// ---------------------------------------------------------------------------
extern "C" void kernel_launch(void* const* d_in, const int* in_sizes, int n_in,
                              void* d_out, int out_size) {
    const float* x  = (const float*)d_in[0];
    const int*   ei = (const int*)  d_in[1];
    const float* ew = (const float*)d_in[2];
    const float* W1 = (const float*)d_in[3];
    const float* b1 = (const float*)d_in[4];
    const float* W2 = (const float*)d_in[5];
    const float* b2 = (const float*)d_in[6];
    const float* W3 = (const float*)d_in[7];
    const float* b3 = (const float*)d_in[8];
    float* out = (float*)d_out;

    const int n = N_NODES;
    const int E = N_EDGES;

    __half *bufHa, *bufHb, *Whi, *Wlo;
    void* p;
    cudaGetSymbolAddress(&p, g_bufHa); bufHa = (__half*)p;
    cudaGetSymbolAddress(&p, g_bufHb); bufHb = (__half*)p;
    cudaGetSymbolAddress(&p, g_Whi);   Whi   = (__half*)p;
    cudaGetSymbolAddress(&p, g_Wlo);   Wlo   = (__half*)p;

    const int TPB = 256;
    int nbE2 = (E / 2 + TPB - 1) / TPB;       // 2 edges per thread
    int nbScan = (n + 1023) / 1024;     // 49

    int gemmBlocks  = (n + 63) / 64;          // BM = 64
    int agg128Blocks = (n * 64 + TPB - 1) / TPB;   // 2 warps per node
    int aggFBlocks   = (n * 32 + TPB - 1) / TPB;   // 1 warp per node

    // ---- fork: side stream for convW + GEMM1 ----
    cudaStream_t sB;
    cudaStreamCreateWithFlags(&sB, cudaStreamNonBlocking);
    cudaEvent_t evFork, evJoin;
    cudaEventCreateWithFlags(&evFork, cudaEventDisableTiming);
    cudaEventCreateWithFlags(&evJoin, cudaEventDisableTiming);

    cudaEventRecord(evFork, 0);
    cudaStreamWaitEvent(sB, evFork, 0);

    // Branch B (tensor-bound): W conversion, then layer-1 GEMM (A_FP32).
    k_convW<<<(W_TOTAL + TPB - 1) / TPB, TPB, 0, sB>>>(W1, W2, W3);
    k_gemm<256, 128, true><<<gemmBlocks, 256, 0, sB>>>(x, Whi + W1_OFF, Wlo + W1_OFF, bufHa, n);
    cudaEventRecord(evJoin, sB);

    // Branch A (memory-bound): CSR build chain on default stream.
    // (g_deg64 pre-zeroed by the previous invocation's final agg kernel.)
    k_deg_count<<<nbE2, TPB>>>(ei, ew, E);
    k_scan1<<<nbScan, 1024>>>(n);           // + dis
    k_scan23<<<nbScan, 1024>>>(n, nbScan);
    k_scatter<<<nbE2, TPB>>>(ei, ew, E);

    // ---- join ----
    cudaStreamWaitEvent(0, evJoin, 0);

    // ---- layer 1 agg (fp16 out, 2 warps/node) ----
    k_agg128<<<agg128Blocks, TPB>>>(bufHa, b1, bufHb, n);

    // ---- layer 2: 128 -> 128, relu ----
    k_gemm<128, 128, false><<<gemmBlocks, 256>>>(bufHb, Whi + W2_OFF, Wlo + W2_OFF, bufHa, n);
    k_agg128<<<agg128Blocks, TPB>>>(bufHa, b2, bufHb, n);

    // ---- layer 3: 128 -> 64, no relu ----
    k_gemm<128, 64, false><<<gemmBlocks, 256>>>(bufHb, Whi + W3_OFF, Wlo + W3_OFF, bufHa, n);
    k_agg_final<<<aggFBlocks, TPB>>>(bufHa, b3, out, n);

    cudaEventDestroy(evFork);
    cudaEventDestroy(evJoin);
    cudaStreamDestroy(sB);
}

// round 16
// speedup vs baseline: 1.1382x; 1.1382x over previous
#include <cuda_runtime.h>
#include <cuda_bf16.h>
#include <cuda_fp16.h>
#include <cstdint>

// ---------------------------------------------------------------------------
// GCN: 3 layers. out = Ahat @ (X @ W) + b, relu on layers 1,2.
//
// R16 = R14 aggs (1 warp/node, uint2 gathers — proven) + R15's unified
// 2-MMA GEMM (A single fp16; layer 1 rounds fp32 X once during staging).
// R15's 2-warps-per-node agg REVERTED (it doubled edge-list reads and
// halved gather width -> 2x L2 requests).
// ---------------------------------------------------------------------------

#define N_NODES 50000
#define N_EDGES 800000

// ----- device scratch (static globals: allocation-free) -----
__device__ unsigned long long g_deg64[N_NODES];   // count<<40 | w_sum*2^20
__device__ float g_dis[N_NODES];
__device__ int   g_offsets[N_NODES];
__device__ int   g_blocksums[64];
__device__ uint2 g_edge[N_EDGES];        // .x = src, .y = float bits of norm
__device__ __half g_bufHa[(size_t)N_NODES * 128];
__device__ __half g_bufHb[(size_t)N_NODES * 128];
__device__ __half g_Whi[256 * 128 + 128 * 128 + 128 * 64];
__device__ __half g_Wlo[256 * 128 + 128 * 128 + 128 * 64];

#define W1_OFF 0
#define W2_OFF (256 * 128)
#define W3_OFF (256 * 128 + 128 * 128)
#define W_TOTAL (256 * 128 + 128 * 128 + 128 * 64)

// ---------------------------------------------------------------------------
// Setup kernels (R14 verbatim)
// ---------------------------------------------------------------------------
__global__ void k_deg_count(const int* __restrict__ ei,
                            const float* __restrict__ ew, int E) {
    int i = blockIdx.x * blockDim.x + threadIdx.x;
    int e = i * 2;
    if (e + 1 < E) {
        int2   d2 = *(const int2*)(ei + E + e);
        float2 w2 = *(const float2*)(ew + e);
        unsigned long long v0 = (1ULL << 40) |
            (unsigned long long)(w2.x * 1048576.0f);
        unsigned long long v1 = (1ULL << 40) |
            (unsigned long long)(w2.y * 1048576.0f);
        atomicAdd(&g_deg64[d2.x], v0);
        atomicAdd(&g_deg64[d2.y], v1);
    } else if (e < E) {
        unsigned long long v = (1ULL << 40) |
            (unsigned long long)(ew[e] * 1048576.0f);
        atomicAdd(&g_deg64[ei[E + e]], v);
    }
}

__global__ void k_scan1(int n) {
    __shared__ int sh[1024];
    int tid = threadIdx.x;
    int gid = blockIdx.x * 1024 + tid;
    int v = 0;
    if (gid < n) {
        unsigned long long pk = g_deg64[gid];
        v = (int)(pk >> 40);
        float deg = (float)(pk & ((1ULL << 40) - 1)) * (1.0f / 1048576.0f);
        g_dis[gid] = rsqrtf(deg + 1.0f);
    }
    sh[tid] = v;
    __syncthreads();
    for (int off = 1; off < 1024; off <<= 1) {
        int t = (tid >= off) ? sh[tid - off] : 0;
        __syncthreads();
        sh[tid] += t;
        __syncthreads();
    }
    int incl = sh[tid];
    if (gid < n) g_offsets[gid] = incl - v;
    if (tid == 1023) g_blocksums[blockIdx.x] = incl;
}

__global__ void k_scan23(int n, int nb) {
    __shared__ int sh[64];
    int tid = threadIdx.x;
    if (tid < 64) sh[tid] = (tid < nb) ? g_blocksums[tid] : 0;
    __syncthreads();
    if (tid == 0) {
        int run = 0;
        for (int i = 0; i < nb; i++) { int t = sh[i]; sh[i] = run; run += t; }
    }
    __syncthreads();
    int gid = blockIdx.x * 1024 + tid;
    if (gid < n) g_offsets[gid] += sh[blockIdx.x];
}

__global__ void k_scatter(const int* __restrict__ ei,
                          const float* __restrict__ ew, int E) {
    int i = blockIdx.x * blockDim.x + threadIdx.x;
    int e = i * 2;
    if (e + 1 < E) {
        int2   s2 = *(const int2*)(ei + e);
        int2   d2 = *(const int2*)(ei + E + e);
        float2 w2 = *(const float2*)(ew + e);
        float ds0 = g_dis[s2.x], dd0 = g_dis[d2.x];
        float ds1 = g_dis[s2.y], dd1 = g_dis[d2.y];
        int pos0 = atomicAdd(&g_offsets[d2.x], 1);
        int pos1 = atomicAdd(&g_offsets[d2.y], 1);
        g_edge[pos0] = make_uint2((uint32_t)s2.x,
                                  __float_as_uint(ds0 * w2.x * dd0));
        g_edge[pos1] = make_uint2((uint32_t)s2.y,
                                  __float_as_uint(ds1 * w2.y * dd1));
    } else if (e < E) {
        int s = ei[e];
        int d = ei[E + e];
        int pos = atomicAdd(&g_offsets[d], 1);
        float nw = g_dis[s] * ew[e] * g_dis[d];
        g_edge[pos] = make_uint2((uint32_t)s, __float_as_uint(nw));
    }
}

// Convert all three W matrices fp32 -> fp16 hi/lo (once per call).
__global__ void k_convW(const float* __restrict__ W1, const float* __restrict__ W2,
                        const float* __restrict__ W3) {
    int i = blockIdx.x * blockDim.x + threadIdx.x;
    if (i >= W_TOTAL) return;
    float v;
    if (i < W2_OFF)       v = W1[i];
    else if (i < W3_OFF)  v = W2[i - W2_OFF];
    else                  v = W3[i - W3_OFF];
    __half h = __float2half_rn(v);
    __half l = __float2half_rn(v - __half2float(h));
    g_Whi[i] = h;
    g_Wlo[i] = l;
}

// ---------------------------------------------------------------------------
// Tensor-core GEMM helpers (fp16 path)
// ---------------------------------------------------------------------------
__device__ __forceinline__ uint32_t smem_u32(const void* p) {
    return (uint32_t)__cvta_generic_to_shared(p);
}

__device__ __forceinline__ void ldsm4(uint32_t a[4], uint32_t addr) {
    asm volatile("ldmatrix.sync.aligned.m8n8.x4.shared.b16 {%0,%1,%2,%3}, [%4];"
                 : "=r"(a[0]), "=r"(a[1]), "=r"(a[2]), "=r"(a[3]) : "r"(addr));
}

__device__ __forceinline__ void ldsm4t(uint32_t a[4], uint32_t addr) {
    asm volatile("ldmatrix.sync.aligned.m8n8.x4.trans.shared.b16 {%0,%1,%2,%3}, [%4];"
                 : "=r"(a[0]), "=r"(a[1]), "=r"(a[2]), "=r"(a[3]) : "r"(addr));
}

__device__ __forceinline__ void mma16816h(float c[4], const uint32_t a[4],
                                          const uint32_t b[2]) {
    asm volatile(
        "mma.sync.aligned.m16n8k16.row.col.f32.f16.f16.f32 "
        "{%0,%1,%2,%3}, {%4,%5,%6,%7}, {%8,%9}, {%0,%1,%2,%3};"
        : "+f"(c[0]), "+f"(c[1]), "+f"(c[2]), "+f"(c[3])
        : "r"(a[0]), "r"(a[1]), "r"(a[2]), "r"(a[3]), "r"(b[0]), "r"(b[1]));
}

// ---------------------------------------------------------------------------
// GEMM (all layers): A = fp16 (direct, or fp32 rounded once during staging),
// W fp16 hi/lo, 2 MMAs per k-step.
// Block: 256 threads = 8 warps (2 M x 4 N). BM=64, BK=64.
// ---------------------------------------------------------------------------
template <int K, int FOUT, bool A_FP32>
__launch_bounds__(256, 2)
__global__ void k_gemm(const void* __restrict__ Ag,
                       const __half* __restrict__ Whi,
                       const __half* __restrict__ Wlo,
                       __half* __restrict__ Yh, int nrows) {
    constexpr int BM = 64, BK = 64, BN = FOUT;
    constexpr int WN = BN / 4;
    constexpr int NT = WN / 8;
    constexpr int NG = WN / 16;
    constexpr int BCH = BN / 8;
    constexpr int BROWB = BN * 2;

    __shared__ __half Ah[BM * BK];
    __shared__ __half Bhi[BK * BN];
    __shared__ __half Blo[BK * BN];

    const int tid  = threadIdx.x;
    const int lane = tid & 31;
    const int w    = tid >> 5;
    const int wm   = (w & 1) * 32;
    const int wn   = (w >> 1) * WN;
    const int row0 = blockIdx.x * BM;

    float acc[2][NT][4];
#pragma unroll
    for (int mt = 0; mt < 2; mt++)
#pragma unroll
        for (int nt = 0; nt < NT; nt++)
#pragma unroll
            for (int j = 0; j < 4; j++) acc[mt][nt][j] = 0.0f;

    const uint32_t sAh = smem_u32(Ah);
    const uint32_t sBhi = smem_u32(Bhi), sBlo = smem_u32(Blo);

    for (int k0 = 0; k0 < K; k0 += BK) {
        // ---- stage A ----
#pragma unroll
        for (int i = 0; i < 2; i++) {          // 512 16B chunks / 256 threads
            int idx = tid + i * 256;
            int r = idx >> 3, c = idx & 7;
            int gr = row0 + r;
            uint4 v;
            if constexpr (A_FP32) {
                if (gr < nrows) {
                    const float4* p = (const float4*)((const float*)Ag +
                                                      (size_t)gr * K + k0 + c * 8);
                    float4 f0 = p[0], f1 = p[1];
                    __half2 h0 = __floats2half2_rn(f0.x, f0.y);
                    __half2 h1 = __floats2half2_rn(f0.z, f0.w);
                    __half2 h2 = __floats2half2_rn(f1.x, f1.y);
                    __half2 h3 = __floats2half2_rn(f1.z, f1.w);
                    v = make_uint4(*(uint32_t*)&h0, *(uint32_t*)&h1,
                                   *(uint32_t*)&h2, *(uint32_t*)&h3);
                } else {
                    v = make_uint4(0, 0, 0, 0);
                }
            } else {
                v = (gr < nrows)
                    ? *(const uint4*)((const __half*)Ag + (size_t)gr * K + k0 + c * 8)
                    : make_uint4(0, 0, 0, 0);
            }
            int dst = r * 128 + ((c ^ (r & 7)) << 4);
            *(uint4*)((char*)Ah + dst) = v;
        }
        // ---- stage B: fp16 hi/lo copies, swizzled ----
        {
            constexpr int CPB = BK * BCH;
#pragma unroll
            for (int i = 0; i < (2 * CPB) / 256; i++) {
                int idx = tid + i * 256;
                int buf = idx / CPB;
                int rem = idx - buf * CPB;
                int kr = rem / BCH, c = rem % BCH;
                const uint4* src = (const uint4*)(buf ? Wlo : Whi);
                uint4 v = src[(size_t)(k0 + kr) * BCH + c];
                int dst = kr * BROWB + ((c ^ (kr & 7)) << 4);
                *(uint4*)((char*)(buf ? Blo : Bhi) + dst) = v;
            }
        }
        __syncthreads();

#pragma unroll
        for (int kk = 0; kk < BK / 16; kk++) {
            uint32_t a[2][4];
#pragma unroll
            for (int mt = 0; mt < 2; mt++) {
                int r = wm + mt * 16 + (lane & 15);
                int c = kk * 2 + (lane >> 4);
                uint32_t off = (uint32_t)(r * 128 + ((c ^ (r & 7)) << 4));
                ldsm4(a[mt], sAh + off);
            }
            uint32_t bh[NG][4], bl[NG][4];
#pragma unroll
            for (int g = 0; g < NG; g++) {
                int kr = kk * 16 + (lane & 15);
                int c = (wn >> 3) + g * 2 + (lane >> 4);
                uint32_t off = (uint32_t)(kr * BROWB + ((c ^ (kr & 7)) << 4));
                ldsm4t(bh[g], sBhi + off);
                ldsm4t(bl[g], sBlo + off);
            }
#pragma unroll
            for (int mt = 0; mt < 2; mt++)
#pragma unroll
                for (int nt = 0; nt < NT; nt++) {
                    const uint32_t* bhp = &bh[nt >> 1][(nt & 1) * 2];
                    const uint32_t* blp = &bl[nt >> 1][(nt & 1) * 2];
                    mma16816h(acc[mt][nt], a[mt], bhp);   // A*Whi
                    mma16816h(acc[mt][nt], a[mt], blp);   // A*Wlo
                }
        }
        __syncthreads();
    }

#pragma unroll
    for (int mt = 0; mt < 2; mt++) {
        int r = row0 + wm + mt * 16 + (lane >> 2);
#pragma unroll
        for (int nt = 0; nt < NT; nt++) {
            int cc = wn + nt * 8 + (lane & 3) * 2;
            if (r < nrows)
                *(__half2*)(Yh + (size_t)r * FOUT + cc) =
                    __floats2half2_rn(acc[mt][nt][0], acc[mt][nt][1]);
            if (r + 8 < nrows)
                *(__half2*)(Yh + (size_t)(r + 8) * FOUT + cc) =
                    __floats2half2_rn(acc[mt][nt][2], acc[mt][nt][3]);
        }
    }
}

// ---------------------------------------------------------------------------
// Aggregation (R14 verbatim): one warp per node, fp16 gathers, fp32 accum.
// FINAL=false: fp16 out (feeds GEMM). FINAL=true: fp32 out + zero g_deg64.
// ---------------------------------------------------------------------------
template <int F, bool RELU, bool FINAL>
__launch_bounds__(256)
__global__ void k_agg(const __half* __restrict__ H, const float* __restrict__ bias,
                      __half* __restrict__ outH, float* __restrict__ outF, int n) {
    int warp = (blockIdx.x * blockDim.x + threadIdx.x) >> 5;
    int lane = threadIdx.x & 31;
    if (warp >= n) return;

    constexpr int VEC = F / 32;          // 4 (F=128) or 2 (F=64)
    int s = (warp == 0) ? 0 : g_offsets[warp - 1];
    int e = g_offsets[warp];
    int col = lane * VEC;

    if constexpr (FINAL) {
        if (lane == 0) g_deg64[warp] = 0ULL;   // reset for next invocation
    }

    if constexpr (VEC == 4) {
        float4 acc = make_float4(0.f, 0.f, 0.f, 0.f);
        for (int j = s; j < e; j++) {
            uint2  ed = g_edge[j];
            float  nw = __uint_as_float(ed.y);
            uint2  raw = *(const uint2*)(H + (size_t)ed.x * F + col);
            float2 f0 = __half22float2(*(__half2*)&raw.x);
            float2 f1 = __half22float2(*(__half2*)&raw.y);
            acc.x += nw * f0.x; acc.y += nw * f0.y;
            acc.z += nw * f1.x; acc.w += nw * f1.y;
        }
        float dv = g_dis[warp];
        float sw = dv * dv;
        uint2 raw = *(const uint2*)(H + (size_t)warp * F + col);
        float2 f0 = __half22float2(*(__half2*)&raw.x);
        float2 f1 = __half22float2(*(__half2*)&raw.y);
        acc.x += sw * f0.x; acc.y += sw * f0.y;
        acc.z += sw * f1.x; acc.w += sw * f1.y;
        float4 b = *(const float4*)(bias + col);
        acc.x += b.x; acc.y += b.y; acc.z += b.z; acc.w += b.w;
        if (RELU) {
            acc.x = fmaxf(acc.x, 0.f); acc.y = fmaxf(acc.y, 0.f);
            acc.z = fmaxf(acc.z, 0.f); acc.w = fmaxf(acc.w, 0.f);
        }
        if constexpr (FINAL) {
            *(float4*)(outF + (size_t)warp * F + col) = acc;
        } else {
            __half2 p0 = __floats2half2_rn(acc.x, acc.y);
            __half2 p1 = __floats2half2_rn(acc.z, acc.w);
            *(uint2*)(outH + (size_t)warp * F + col) =
                make_uint2(*(uint32_t*)&p0, *(uint32_t*)&p1);
        }
    } else {
        float2 acc = make_float2(0.f, 0.f);
        for (int j = s; j < e; j++) {
            uint2  ed = g_edge[j];
            float  nw = __uint_as_float(ed.y);
            uint32_t raw = *(const uint32_t*)(H + (size_t)ed.x * F + col);
            float2 f0 = __half22float2(*(__half2*)&raw);
            acc.x += nw * f0.x; acc.y += nw * f0.y;
        }
        float dv = g_dis[warp];
        float sw = dv * dv;
        uint32_t raw = *(const uint32_t*)(H + (size_t)warp * F + col);
        float2 f0 = __half22float2(*(__half2*)&raw);
        acc.x += sw * f0.x; acc.y += sw * f0.y;
        float2 b = *(const float2*)(bias + col);
        acc.x += b.x; acc.y += b.y;
        if (RELU) { acc.x = fmaxf(acc.x, 0.f); acc.y = fmaxf(acc.y, 0.f); }
        if constexpr (FINAL) {
            *(float2*)(outF + (size_t)warp * F + col) = acc;
        } else {
            __half2 p0 = __floats2half2_rn(acc.x, acc.y);
            *(uint32_t*)(outH + (size_t)warp * F + col) = *(uint32_t*)&p0;
        }
    }
}

// ---------------------------------------------------------------------------
// Launch: fork-join (branch A: CSR build; branch B: convW + GEMM1).
// ---------------------------------------------------------------------------
extern "C" void kernel_launch(void* const* d_in, const int* in_sizes, int n_in,
                              void* d_out, int out_size) {
    const float* x  = (const float*)d_in[0];
    const int*   ei = (const int*)  d_in[1];
    const float* ew = (const float*)d_in[2];
    const float* W1 = (const float*)d_in[3];
    const float* b1 = (const float*)d_in[4];
    const float* W2 = (const float*)d_in[5];
    const float* b2 = (const float*)d_in[6];
    const float* W3 = (const float*)d_in[7];
    const float* b3 = (const float*)d_in[8];
    float* out = (float*)d_out;

    const int n = N_NODES;
    const int E = N_EDGES;

    __half *bufHa, *bufHb, *Whi, *Wlo;
    void* p;
    cudaGetSymbolAddress(&p, g_bufHa); bufHa = (__half*)p;
    cudaGetSymbolAddress(&p, g_bufHb); bufHb = (__half*)p;
    cudaGetSymbolAddress(&p, g_Whi);   Whi   = (__half*)p;
    cudaGetSymbolAddress(&p, g_Wlo);   Wlo   = (__half*)p;

    const int TPB = 256;
    int nbE2 = (E / 2 + TPB - 1) / TPB;       // 2 edges per thread
    int nbScan = (n + 1023) / 1024;     // 49

    int gemmBlocks = (n + 63) / 64;      // BM = 64
    int aggBlocks  = (n * 32 + TPB - 1) / TPB;   // 1 warp per node

    // ---- fork: side stream for convW + GEMM1 ----
    cudaStream_t sB;
    cudaStreamCreateWithFlags(&sB, cudaStreamNonBlocking);
    cudaEvent_t evFork, evJoin;
    cudaEventCreateWithFlags(&evFork, cudaEventDisableTiming);
    cudaEventCreateWithFlags(&evJoin, cudaEventDisableTiming);

    cudaEventRecord(evFork, 0);
    cudaStreamWaitEvent(sB, evFork, 0);

    // Branch B (tensor-bound): W conversion, then layer-1 GEMM (A_FP32).
    k_convW<<<(W_TOTAL + TPB - 1) / TPB, TPB, 0, sB>>>(W1, W2, W3);
    k_gemm<256, 128, true><<<gemmBlocks, 256, 0, sB>>>(x, Whi + W1_OFF, Wlo + W1_OFF, bufHa, n);
    cudaEventRecord(evJoin, sB);

    // Branch A (memory-bound): CSR build chain on default stream.
    // (g_deg64 pre-zeroed by the previous invocation's final agg kernel.)
    k_deg_count<<<nbE2, TPB>>>(ei, ew, E);
    k_scan1<<<nbScan, 1024>>>(n);           // + dis
    k_scan23<<<nbScan, 1024>>>(n, nbScan);
    k_scatter<<<nbE2, TPB>>>(ei, ew, E);

    // ---- join ----
    cudaStreamWaitEvent(0, evJoin, 0);

    // ---- layer 1 agg (fp16 out) ----
    k_agg<128, true, false><<<aggBlocks, TPB>>>(bufHa, b1, bufHb, nullptr, n);

    // ---- layer 2: 128 -> 128, relu ----
    k_gemm<128, 128, false><<<gemmBlocks, 256>>>(bufHb, Whi + W2_OFF, Wlo + W2_OFF, bufHa, n);
    k_agg<128, true, false><<<aggBlocks, TPB>>>(bufHa, b2, bufHb, nullptr, n);

    // ---- layer 3: 128 -> 64, no relu ----
    k_gemm<128, 64, false><<<gemmBlocks, 256>>>(bufHb, Whi + W3_OFF, Wlo + W3_OFF, bufHa, n);
    k_agg<64, false, true><<<aggBlocks, TPB>>>(bufHa, b3, nullptr, out, n);

    cudaEventDestroy(evFork);
    cudaEventDestroy(evJoin);
    cudaStreamDestroy(sB);
}

// round 17
// speedup vs baseline: 1.2537x; 1.1014x over previous
#include <cuda_runtime.h>
#include <cuda_bf16.h>
#include <cuda_fp16.h>
#include <cstdint>

// ---------------------------------------------------------------------------
// GCN: 3 layers. out = Ahat @ (X @ W) + b, relu on layers 1,2.
//
// R17 = R16 with single-fp16 W (no hi/lo split): 1 MMA per k-step, half the
// B staging/smem in every GEMM. Error budget justified by R16's measurement
// that operand fp16 rounding barely moves rel_err (H-storage dominates).
// CSR chain / fork-join / aggs unchanged from R16.
// ---------------------------------------------------------------------------

#define N_NODES 50000
#define N_EDGES 800000

// ----- device scratch (static globals: allocation-free) -----
__device__ unsigned long long g_deg64[N_NODES];   // count<<40 | w_sum*2^20
__device__ float g_dis[N_NODES];
__device__ int   g_offsets[N_NODES];
__device__ int   g_blocksums[64];
__device__ uint2 g_edge[N_EDGES];        // .x = src, .y = float bits of norm
__device__ __half g_bufHa[(size_t)N_NODES * 128];
__device__ __half g_bufHb[(size_t)N_NODES * 128];
__device__ __half g_Wh[256 * 128 + 128 * 128 + 128 * 64];

#define W1_OFF 0
#define W2_OFF (256 * 128)
#define W3_OFF (256 * 128 + 128 * 128)
#define W_TOTAL (256 * 128 + 128 * 128 + 128 * 64)

// ---------------------------------------------------------------------------
// Setup kernels (R16 verbatim)
// ---------------------------------------------------------------------------
__global__ void k_deg_count(const int* __restrict__ ei,
                            const float* __restrict__ ew, int E) {
    int i = blockIdx.x * blockDim.x + threadIdx.x;
    int e = i * 2;
    if (e + 1 < E) {
        int2   d2 = *(const int2*)(ei + E + e);
        float2 w2 = *(const float2*)(ew + e);
        unsigned long long v0 = (1ULL << 40) |
            (unsigned long long)(w2.x * 1048576.0f);
        unsigned long long v1 = (1ULL << 40) |
            (unsigned long long)(w2.y * 1048576.0f);
        atomicAdd(&g_deg64[d2.x], v0);
        atomicAdd(&g_deg64[d2.y], v1);
    } else if (e < E) {
        unsigned long long v = (1ULL << 40) |
            (unsigned long long)(ew[e] * 1048576.0f);
        atomicAdd(&g_deg64[ei[E + e]], v);
    }
}

__global__ void k_scan1(int n) {
    __shared__ int sh[1024];
    int tid = threadIdx.x;
    int gid = blockIdx.x * 1024 + tid;
    int v = 0;
    if (gid < n) {
        unsigned long long pk = g_deg64[gid];
        v = (int)(pk >> 40);
        float deg = (float)(pk & ((1ULL << 40) - 1)) * (1.0f / 1048576.0f);
        g_dis[gid] = rsqrtf(deg + 1.0f);
    }
    sh[tid] = v;
    __syncthreads();
    for (int off = 1; off < 1024; off <<= 1) {
        int t = (tid >= off) ? sh[tid - off] : 0;
        __syncthreads();
        sh[tid] += t;
        __syncthreads();
    }
    int incl = sh[tid];
    if (gid < n) g_offsets[gid] = incl - v;
    if (tid == 1023) g_blocksums[blockIdx.x] = incl;
}

__global__ void k_scan23(int n, int nb) {
    __shared__ int sh[64];
    int tid = threadIdx.x;
    if (tid < 64) sh[tid] = (tid < nb) ? g_blocksums[tid] : 0;
    __syncthreads();
    if (tid == 0) {
        int run = 0;
        for (int i = 0; i < nb; i++) { int t = sh[i]; sh[i] = run; run += t; }
    }
    __syncthreads();
    int gid = blockIdx.x * 1024 + tid;
    if (gid < n) g_offsets[gid] += sh[blockIdx.x];
}

__global__ void k_scatter(const int* __restrict__ ei,
                          const float* __restrict__ ew, int E) {
    int i = blockIdx.x * blockDim.x + threadIdx.x;
    int e = i * 2;
    if (e + 1 < E) {
        int2   s2 = *(const int2*)(ei + e);
        int2   d2 = *(const int2*)(ei + E + e);
        float2 w2 = *(const float2*)(ew + e);
        float ds0 = g_dis[s2.x], dd0 = g_dis[d2.x];
        float ds1 = g_dis[s2.y], dd1 = g_dis[d2.y];
        int pos0 = atomicAdd(&g_offsets[d2.x], 1);
        int pos1 = atomicAdd(&g_offsets[d2.y], 1);
        g_edge[pos0] = make_uint2((uint32_t)s2.x,
                                  __float_as_uint(ds0 * w2.x * dd0));
        g_edge[pos1] = make_uint2((uint32_t)s2.y,
                                  __float_as_uint(ds1 * w2.y * dd1));
    } else if (e < E) {
        int s = ei[e];
        int d = ei[E + e];
        int pos = atomicAdd(&g_offsets[d], 1);
        float nw = g_dis[s] * ew[e] * g_dis[d];
        g_edge[pos] = make_uint2((uint32_t)s, __float_as_uint(nw));
    }
}

// Convert all three W matrices fp32 -> fp16 (single, rounded once).
__global__ void k_convW(const float* __restrict__ W1, const float* __restrict__ W2,
                        const float* __restrict__ W3) {
    int i = blockIdx.x * blockDim.x + threadIdx.x;
    if (i >= W_TOTAL) return;
    float v;
    if (i < W2_OFF)       v = W1[i];
    else if (i < W3_OFF)  v = W2[i - W2_OFF];
    else                  v = W3[i - W3_OFF];
    g_Wh[i] = __float2half_rn(v);
}

// ---------------------------------------------------------------------------
// Tensor-core GEMM helpers (fp16 path)
// ---------------------------------------------------------------------------
__device__ __forceinline__ uint32_t smem_u32(const void* p) {
    return (uint32_t)__cvta_generic_to_shared(p);
}

__device__ __forceinline__ void ldsm4(uint32_t a[4], uint32_t addr) {
    asm volatile("ldmatrix.sync.aligned.m8n8.x4.shared.b16 {%0,%1,%2,%3}, [%4];"
                 : "=r"(a[0]), "=r"(a[1]), "=r"(a[2]), "=r"(a[3]) : "r"(addr));
}

__device__ __forceinline__ void ldsm4t(uint32_t a[4], uint32_t addr) {
    asm volatile("ldmatrix.sync.aligned.m8n8.x4.trans.shared.b16 {%0,%1,%2,%3}, [%4];"
                 : "=r"(a[0]), "=r"(a[1]), "=r"(a[2]), "=r"(a[3]) : "r"(addr));
}

__device__ __forceinline__ void mma16816h(float c[4], const uint32_t a[4],
                                          const uint32_t b[2]) {
    asm volatile(
        "mma.sync.aligned.m16n8k16.row.col.f32.f16.f16.f32 "
        "{%0,%1,%2,%3}, {%4,%5,%6,%7}, {%8,%9}, {%0,%1,%2,%3};"
        : "+f"(c[0]), "+f"(c[1]), "+f"(c[2]), "+f"(c[3])
        : "r"(a[0]), "r"(a[1]), "r"(a[2]), "r"(a[3]), "r"(b[0]), "r"(b[1]));
}

// ---------------------------------------------------------------------------
// GEMM (all layers): A = fp16 (direct, or fp32 rounded once during staging),
// W single fp16, 1 MMA per k-step.
// Block: 256 threads = 8 warps (2 M x 4 N). BM=64, BK=64.
// ---------------------------------------------------------------------------
template <int K, int FOUT, bool A_FP32>
__launch_bounds__(256, 2)
__global__ void k_gemm(const void* __restrict__ Ag,
                       const __half* __restrict__ Wh,
                       __half* __restrict__ Yh, int nrows) {
    constexpr int BM = 64, BK = 64, BN = FOUT;
    constexpr int WN = BN / 4;
    constexpr int NT = WN / 8;
    constexpr int NG = WN / 16;
    constexpr int BCH = BN / 8;
    constexpr int BROWB = BN * 2;

    __shared__ __half Ah[BM * BK];
    __shared__ __half Bh[BK * BN];

    const int tid  = threadIdx.x;
    const int lane = tid & 31;
    const int w    = tid >> 5;
    const int wm   = (w & 1) * 32;
    const int wn   = (w >> 1) * WN;
    const int row0 = blockIdx.x * BM;

    float acc[2][NT][4];
#pragma unroll
    for (int mt = 0; mt < 2; mt++)
#pragma unroll
        for (int nt = 0; nt < NT; nt++)
#pragma unroll
            for (int j = 0; j < 4; j++) acc[mt][nt][j] = 0.0f;

    const uint32_t sAh = smem_u32(Ah);
    const uint32_t sBh = smem_u32(Bh);

    for (int k0 = 0; k0 < K; k0 += BK) {
        // ---- stage A ----
#pragma unroll
        for (int i = 0; i < 2; i++) {          // 512 16B chunks / 256 threads
            int idx = tid + i * 256;
            int r = idx >> 3, c = idx & 7;
            int gr = row0 + r;
            uint4 v;
            if constexpr (A_FP32) {
                if (gr < nrows) {
                    const float4* p = (const float4*)((const float*)Ag +
                                                      (size_t)gr * K + k0 + c * 8);
                    float4 f0 = p[0], f1 = p[1];
                    __half2 h0 = __floats2half2_rn(f0.x, f0.y);
                    __half2 h1 = __floats2half2_rn(f0.z, f0.w);
                    __half2 h2 = __floats2half2_rn(f1.x, f1.y);
                    __half2 h3 = __floats2half2_rn(f1.z, f1.w);
                    v = make_uint4(*(uint32_t*)&h0, *(uint32_t*)&h1,
                                   *(uint32_t*)&h2, *(uint32_t*)&h3);
                } else {
                    v = make_uint4(0, 0, 0, 0);
                }
            } else {
                v = (gr < nrows)
                    ? *(const uint4*)((const __half*)Ag + (size_t)gr * K + k0 + c * 8)
                    : make_uint4(0, 0, 0, 0);
            }
            int dst = r * 128 + ((c ^ (r & 7)) << 4);
            *(uint4*)((char*)Ah + dst) = v;
        }
        // ---- stage B: single fp16 copies, swizzled ----
        {
            constexpr int CPB = BK * BCH;      // 16B chunks (1024 or 512)
#pragma unroll
            for (int i = 0; i < CPB / 256; i++) {
                int idx = tid + i * 256;
                int kr = idx / BCH, c = idx % BCH;
                uint4 v = ((const uint4*)Wh)[(size_t)(k0 + kr) * BCH + c];
                int dst = kr * BROWB + ((c ^ (kr & 7)) << 4);
                *(uint4*)((char*)Bh + dst) = v;
            }
        }
        __syncthreads();

#pragma unroll
        for (int kk = 0; kk < BK / 16; kk++) {
            uint32_t a[2][4];
#pragma unroll
            for (int mt = 0; mt < 2; mt++) {
                int r = wm + mt * 16 + (lane & 15);
                int c = kk * 2 + (lane >> 4);
                uint32_t off = (uint32_t)(r * 128 + ((c ^ (r & 7)) << 4));
                ldsm4(a[mt], sAh + off);
            }
            uint32_t bh[NG][4];
#pragma unroll
            for (int g = 0; g < NG; g++) {
                int kr = kk * 16 + (lane & 15);
                int c = (wn >> 3) + g * 2 + (lane >> 4);
                uint32_t off = (uint32_t)(kr * BROWB + ((c ^ (kr & 7)) << 4));
                ldsm4t(bh[g], sBh + off);
            }
#pragma unroll
            for (int mt = 0; mt < 2; mt++)
#pragma unroll
                for (int nt = 0; nt < NT; nt++) {
                    const uint32_t* bhp = &bh[nt >> 1][(nt & 1) * 2];
                    mma16816h(acc[mt][nt], a[mt], bhp);
                }
        }
        __syncthreads();
    }

#pragma unroll
    for (int mt = 0; mt < 2; mt++) {
        int r = row0 + wm + mt * 16 + (lane >> 2);
#pragma unroll
        for (int nt = 0; nt < NT; nt++) {
            int cc = wn + nt * 8 + (lane & 3) * 2;
            if (r < nrows)
                *(__half2*)(Yh + (size_t)r * FOUT + cc) =
                    __floats2half2_rn(acc[mt][nt][0], acc[mt][nt][1]);
            if (r + 8 < nrows)
                *(__half2*)(Yh + (size_t)(r + 8) * FOUT + cc) =
                    __floats2half2_rn(acc[mt][nt][2], acc[mt][nt][3]);
        }
    }
}

// ---------------------------------------------------------------------------
// Aggregation (R16 verbatim): one warp per node, fp16 gathers, fp32 accum.
// FINAL=false: fp16 out (feeds GEMM). FINAL=true: fp32 out + zero g_deg64.
// ---------------------------------------------------------------------------
template <int F, bool RELU, bool FINAL>
__launch_bounds__(256)
__global__ void k_agg(const __half* __restrict__ H, const float* __restrict__ bias,
                      __half* __restrict__ outH, float* __restrict__ outF, int n) {
    int warp = (blockIdx.x * blockDim.x + threadIdx.x) >> 5;
    int lane = threadIdx.x & 31;
    if (warp >= n) return;

    constexpr int VEC = F / 32;          // 4 (F=128) or 2 (F=64)
    int s = (warp == 0) ? 0 : g_offsets[warp - 1];
    int e = g_offsets[warp];
    int col = lane * VEC;

    if constexpr (FINAL) {
        if (lane == 0) g_deg64[warp] = 0ULL;   // reset for next invocation
    }

    if constexpr (VEC == 4) {
        float4 acc = make_float4(0.f, 0.f, 0.f, 0.f);
        for (int j = s; j < e; j++) {
            uint2  ed = g_edge[j];
            float  nw = __uint_as_float(ed.y);
            uint2  raw = *(const uint2*)(H + (size_t)ed.x * F + col);
            float2 f0 = __half22float2(*(__half2*)&raw.x);
            float2 f1 = __half22float2(*(__half2*)&raw.y);
            acc.x += nw * f0.x; acc.y += nw * f0.y;
            acc.z += nw * f1.x; acc.w += nw * f1.y;
        }
        float dv = g_dis[warp];
        float sw = dv * dv;
        uint2 raw = *(const uint2*)(H + (size_t)warp * F + col);
        float2 f0 = __half22float2(*(__half2*)&raw.x);
        float2 f1 = __half22float2(*(__half2*)&raw.y);
        acc.x += sw * f0.x; acc.y += sw * f0.y;
        acc.z += sw * f1.x; acc.w += sw * f1.y;
        float4 b = *(const float4*)(bias + col);
        acc.x += b.x; acc.y += b.y; acc.z += b.z; acc.w += b.w;
        if (RELU) {
            acc.x = fmaxf(acc.x, 0.f); acc.y = fmaxf(acc.y, 0.f);
            acc.z = fmaxf(acc.z, 0.f); acc.w = fmaxf(acc.w, 0.f);
        }
        if constexpr (FINAL) {
            *(float4*)(outF + (size_t)warp * F + col) = acc;
        } else {
            __half2 p0 = __floats2half2_rn(acc.x, acc.y);
            __half2 p1 = __floats2half2_rn(acc.z, acc.w);
            *(uint2*)(outH + (size_t)warp * F + col) =
                make_uint2(*(uint32_t*)&p0, *(uint32_t*)&p1);
        }
    } else {
        float2 acc = make_float2(0.f, 0.f);
        for (int j = s; j < e; j++) {
            uint2  ed = g_edge[j];
            float  nw = __uint_as_float(ed.y);
            uint32_t raw = *(const uint32_t*)(H + (size_t)ed.x * F + col);
            float2 f0 = __half22float2(*(__half2*)&raw);
            acc.x += nw * f0.x; acc.y += nw * f0.y;
        }
        float dv = g_dis[warp];
        float sw = dv * dv;
        uint32_t raw = *(const uint32_t*)(H + (size_t)warp * F + col);
        float2 f0 = __half22float2(*(__half2*)&raw);
        acc.x += sw * f0.x; acc.y += sw * f0.y;
        float2 b = *(const float2*)(bias + col);
        acc.x += b.x; acc.y += b.y;
        if (RELU) { acc.x = fmaxf(acc.x, 0.f); acc.y = fmaxf(acc.y, 0.f); }
        if constexpr (FINAL) {
            *(float2*)(outF + (size_t)warp * F + col) = acc;
        } else {
            __half2 p0 = __floats2half2_rn(acc.x, acc.y);
            *(uint32_t*)(outH + (size_t)warp * F + col) = *(uint32_t*)&p0;
        }
    }
}

// ---------------------------------------------------------------------------
// Launch: fork-join (branch A: CSR build; branch B: convW + GEMM1).
// ---------------------------------------------------------------------------
extern "C" void kernel_launch(void* const* d_in, const int* in_sizes, int n_in,
                              void* d_out, int out_size) {
    const float* x  = (const float*)d_in[0];
    const int*   ei = (const int*)  d_in[1];
    const float* ew = (const float*)d_in[2];
    const float* W1 = (const float*)d_in[3];
    const float* b1 = (const float*)d_in[4];
    const float* W2 = (const float*)d_in[5];
    const float* b2 = (const float*)d_in[6];
    const float* W3 = (const float*)d_in[7];
    const float* b3 = (const float*)d_in[8];
    float* out = (float*)d_out;

    const int n = N_NODES;
    const int E = N_EDGES;

    __half *bufHa, *bufHb, *Wh;
    void* p;
    cudaGetSymbolAddress(&p, g_bufHa); bufHa = (__half*)p;
    cudaGetSymbolAddress(&p, g_bufHb); bufHb = (__half*)p;
    cudaGetSymbolAddress(&p, g_Wh);    Wh    = (__half*)p;

    const int TPB = 256;
    int nbE2 = (E / 2 + TPB - 1) / TPB;       // 2 edges per thread
    int nbScan = (n + 1023) / 1024;     // 49

    int gemmBlocks = (n + 63) / 64;      // BM = 64
    int aggBlocks  = (n * 32 + TPB - 1) / TPB;   // 1 warp per node

    // ---- fork: side stream for convW + GEMM1 ----
    cudaStream_t sB;
    cudaStreamCreateWithFlags(&sB, cudaStreamNonBlocking);
    cudaEvent_t evFork, evJoin;
    cudaEventCreateWithFlags(&evFork, cudaEventDisableTiming);
    cudaEventCreateWithFlags(&evJoin, cudaEventDisableTiming);

    cudaEventRecord(evFork, 0);
    cudaStreamWaitEvent(sB, evFork, 0);

    // Branch B (tensor-bound): W conversion, then layer-1 GEMM (A_FP32).
    k_convW<<<(W_TOTAL + TPB - 1) / TPB, TPB, 0, sB>>>(W1, W2, W3);
    k_gemm<256, 128, true><<<gemmBlocks, 256, 0, sB>>>(x, Wh + W1_OFF, bufHa, n);
    cudaEventRecord(evJoin, sB);

    // Branch A (memory-bound): CSR build chain on default stream.
    // (g_deg64 pre-zeroed by the previous invocation's final agg kernel.)
    k_deg_count<<<nbE2, TPB>>>(ei, ew, E);
    k_scan1<<<nbScan, 1024>>>(n);           // + dis
    k_scan23<<<nbScan, 1024>>>(n, nbScan);
    k_scatter<<<nbE2, TPB>>>(ei, ew, E);

    // ---- join ----
    cudaStreamWaitEvent(0, evJoin, 0);

    // ---- layer 1 agg (fp16 out) ----
    k_agg<128, true, false><<<aggBlocks, TPB>>>(bufHa, b1, bufHb, nullptr, n);

    // ---- layer 2: 128 -> 128, relu ----
    k_gemm<128, 128, false><<<gemmBlocks, 256>>>(bufHb, Wh + W2_OFF, bufHa, n);
    k_agg<128, true, false><<<aggBlocks, TPB>>>(bufHa, b2, bufHb, nullptr, n);

    // ---- layer 3: 128 -> 64, no relu ----
    k_gemm<128, 64, false><<<gemmBlocks, 256>>>(bufHb, Wh + W3_OFF, bufHa, n);
    k_agg<64, false, true><<<aggBlocks, TPB>>>(bufHa, b3, nullptr, out, n);

    cudaEventDestroy(evFork);
    cudaEventDestroy(evJoin);
    cudaStreamDestroy(sB);
}